// round 14
// baseline (speedup 1.0000x reference)
#include <cuda_runtime.h>
#include <cuda_bf16.h>
#include <cstdint>

// EMA: y_t = w*x_t + (1-w)*y_{t-1}, per-channel w, y_{-1} = initial_state.
// inputs [B,T,C] f32, initial_state [B,C] f32, smooth [C] f32 -> out [B,T,C] f32.
//
// Chunked scan exploiting the data-INDEPENDENT decay a = 1-w: an L-step
// segment's composition factor is analytically a^L, so carries propagate
// without a coefficient scan over the data.
//
// 3 passes, per batch-GROUP (8 batches = 67 MB input < 126 MB L2) so the
// group's input stays L2-resident between pass1 and pass3:
//   pass1: per-(b,s,c4) segment partial B (zero carry); streams x from DRAM
//   pass2: warp per (b,c4): Kogge-Stone scan of segment partials with the
//          analytic coefficient aL = a^L; writes per-segment entry carries
//   pass3: per-(b,s,c4) final scan with known carry; re-reads x (L2 hit,
//          __ldcs: last use), writes out with __stcs (evict-first) so output
//          never evicts unread x from L2.

#define MAX_SCRATCH (16 * 256 * 64)     // B * S_max * C4 for the fixed shape

__device__ float4 g_Bseg[MAX_SCRATCH];   // 4 MiB scratch
__device__ float4 g_carry[MAX_SCRATCH];  // 4 MiB scratch

static __device__ __forceinline__ float clip01(float v) {
    return fminf(fmaxf(v, 0.0f), 1.0f);
}

static __device__ __forceinline__ float4 f4_pow(float4 base, int e) {
    float4 r = make_float4(1.f, 1.f, 1.f, 1.f);
    while (e) {
        if (e & 1) { r.x *= base.x; r.y *= base.y; r.z *= base.z; r.w *= base.w; }
        base.x *= base.x; base.y *= base.y; base.z *= base.z; base.w *= base.w;
        e >>= 1;
    }
    return r;
}

static __device__ __forceinline__ float4 load_wa(const float* __restrict__ smooth,
                                                 int c4, float4* a_out) {
    float4 w = reinterpret_cast<const float4*>(smooth)[c4];
    w.x = clip01(w.x); w.y = clip01(w.y); w.z = clip01(w.z); w.w = clip01(w.w);
    *a_out = make_float4(1.0f - w.x, 1.0f - w.y, 1.0f - w.z, 1.0f - w.w);
    return w;
}

__global__ void __launch_bounds__(256)
ema_pass1(const float4* __restrict__ x,
          const float* __restrict__ smooth,
          int Bg, int T, int C4, int S, int L) {
    int g = blockIdx.x * blockDim.x + threadIdx.x;
    int total = Bg * S * C4;
    if (g >= total) return;
    int c4  = g % C4;
    int rem = g / C4;
    int s   = rem % S;
    int b   = rem / S;

    float4 a;
    float4 w = load_wa(smooth, c4, &a);

    const float4* p = x + (size_t)(b * T + s * L) * C4 + c4;
    const size_t step = (size_t)C4;
    float4 y = make_float4(0.f, 0.f, 0.f, 0.f);

    // Batches of 8 independent loads (MLP=8), then the dependent FMA chain.
    for (int t0 = 0; t0 < L; t0 += 8) {
        float4 v[8];
        #pragma unroll
        for (int i = 0; i < 8; i++) v[i] = p[i * step];
        p += 8 * step;
        #pragma unroll
        for (int i = 0; i < 8; i++) {
            y.x = fmaf(a.x, y.x, w.x * v[i].x);
            y.y = fmaf(a.y, y.y, w.y * v[i].y);
            y.z = fmaf(a.z, y.z, w.z * v[i].z);
            y.w = fmaf(a.w, y.w, w.w * v[i].w);
        }
    }
    g_Bseg[(b * S + s) * C4 + c4] = y;
}

// One WARP per (b, c4). Lane owns spl = S/32 consecutive segments.
__global__ void __launch_bounds__(256)
ema_pass2(const float4* __restrict__ init,
          const float* __restrict__ smooth,
          int Bg, int C4, int S, int L) {
    int warp = (blockIdx.x * blockDim.x + threadIdx.x) >> 5;
    int lane = threadIdx.x & 31;
    int total_warps = Bg * C4;
    if (warp >= total_warps) return;
    int c4 = warp % C4;
    int b  = warp / C4;

    int spl = S >> 5;                 // segments per lane (<= 8)

    float4 a;
    load_wa(smooth, c4, &a);
    float4 aL = f4_pow(a, L);         // per-segment coefficient
    float4 c  = f4_pow(aL, spl);      // per-lane composite coefficient

    // Load this lane's segment partials (independent loads, MLP = spl)
    float4 Bs[8];
    int base = (b * S + lane * spl) * C4 + c4;
    #pragma unroll
    for (int i = 0; i < 8; i++) {
        if (i < spl) Bs[i] = g_Bseg[base + i * C4];
    }

    // Lane-local composite B over its spl segments
    float4 b8 = make_float4(0.f, 0.f, 0.f, 0.f);
    #pragma unroll
    for (int i = 0; i < 8; i++) {
        if (i < spl) {
            b8.x = fmaf(aL.x, b8.x, Bs[i].x);
            b8.y = fmaf(aL.y, b8.y, Bs[i].y);
            b8.z = fmaf(aL.z, b8.z, Bs[i].z);
            b8.w = fmaf(aL.w, b8.w, Bs[i].w);
        }
    }

    // Kogge-Stone inclusive scan of B-terms with constant coefficient c:
    // Bi(l) = sum_{j<=l} c^(l-j) * b8_j
    float4 Bi = b8;
    float4 cd = c;
    #pragma unroll
    for (int d = 1; d < 32; d <<= 1) {
        float4 up;
        up.x = __shfl_up_sync(0xFFFFFFFFu, Bi.x, d);
        up.y = __shfl_up_sync(0xFFFFFFFFu, Bi.y, d);
        up.z = __shfl_up_sync(0xFFFFFFFFu, Bi.z, d);
        up.w = __shfl_up_sync(0xFFFFFFFFu, Bi.w, d);
        if (lane >= d) {
            Bi.x = fmaf(cd.x, up.x, Bi.x);
            Bi.y = fmaf(cd.y, up.y, Bi.y);
            Bi.z = fmaf(cd.z, up.z, Bi.z);
            Bi.w = fmaf(cd.w, up.w, Bi.w);
        }
        cd.x *= cd.x; cd.y *= cd.y; cd.z *= cd.z; cd.w *= cd.w;
    }

    // Exclusive B and analytic exclusive A = c^lane
    float4 Bex;
    Bex.x = __shfl_up_sync(0xFFFFFFFFu, Bi.x, 1);
    Bex.y = __shfl_up_sync(0xFFFFFFFFu, Bi.y, 1);
    Bex.z = __shfl_up_sync(0xFFFFFFFFu, Bi.z, 1);
    Bex.w = __shfl_up_sync(0xFFFFFFFFu, Bi.w, 1);
    if (lane == 0) Bex = make_float4(0.f, 0.f, 0.f, 0.f);
    float4 Aex = f4_pow(c, lane);

    float4 y0 = init[b * C4 + c4];
    float4 carry;
    carry.x = fmaf(Aex.x, y0.x, Bex.x);
    carry.y = fmaf(Aex.y, y0.y, Bex.y);
    carry.z = fmaf(Aex.z, y0.z, Bex.z);
    carry.w = fmaf(Aex.w, y0.w, Bex.w);

    // Write per-segment entry carries for this lane's segments
    #pragma unroll
    for (int i = 0; i < 8; i++) {
        if (i < spl) {
            g_carry[base + i * C4] = carry;
            carry.x = fmaf(aL.x, carry.x, Bs[i].x);
            carry.y = fmaf(aL.y, carry.y, Bs[i].y);
            carry.z = fmaf(aL.z, carry.z, Bs[i].z);
            carry.w = fmaf(aL.w, carry.w, Bs[i].w);
        }
    }
}

__global__ void __launch_bounds__(256)
ema_pass3(const float4* __restrict__ x,
          const float* __restrict__ smooth,
          float4* __restrict__ out,
          int Bg, int T, int C4, int S, int L) {
    int g = blockIdx.x * blockDim.x + threadIdx.x;
    int total = Bg * S * C4;
    if (g >= total) return;
    int c4  = g % C4;
    int rem = g / C4;
    int s   = rem % S;
    int b   = rem / S;

    float4 a;
    float4 w = load_wa(smooth, c4, &a);

    float4 y = g_carry[(b * S + s) * C4 + c4];

    size_t off = (size_t)(b * T + s * L) * C4 + c4;
    const float4* p = x + off;
    float4* q = out + off;
    const size_t step = (size_t)C4;

    for (int t0 = 0; t0 < L; t0 += 8) {
        float4 v[8];
        #pragma unroll
        for (int i = 0; i < 8; i++) v[i] = __ldcs(p + i * step);  // last use
        p += 8 * step;
        #pragma unroll
        for (int i = 0; i < 8; i++) {
            y.x = fmaf(a.x, y.x, w.x * v[i].x);
            y.y = fmaf(a.y, y.y, w.y * v[i].y);
            y.z = fmaf(a.z, y.z, w.z * v[i].z);
            y.w = fmaf(a.w, y.w, w.w * v[i].w);
            __stcs(q + i * step, y);   // streaming store: don't evict x from L2
        }
        q += 8 * step;
    }
}

extern "C" void kernel_launch(void* const* d_in, const int* in_sizes, int n_in,
                              void* d_out, int out_size) {
    const float* x      = (const float*)d_in[0];  // [B,T,C]
    const float* init   = (const float*)d_in[1];  // [B,C]
    const float* smooth = (const float*)d_in[2];  // [C]

    const int C  = in_sizes[2];
    const int B  = in_sizes[1] / C;
    const int T  = in_sizes[0] / (B * C);
    const int C4 = C / 4;

    // Pick S: multiple of 32 (warp scan), divides T, L multiple of 8,
    // spl <= 8, fits scratch.  For T=8192 -> S=256, L=32.
    int S = 0;
    for (int cand = 256; cand >= 32; cand >>= 1) {
        if (T % cand == 0 && ((T / cand) % 8 == 0) &&
            (long long)B * cand * C4 <= MAX_SCRATCH) { S = cand; break; }
    }
    if (S == 0) S = 32;
    const int L = T / S;

    // Batch groups: smallest split whose group input fits L2 with headroom
    // (<= ~80 MB). For B=16,T=8192,C=256 -> groups=2, Bg=8 (67 MB/group).
    const size_t bytes_per_batch = (size_t)T * C * 4;
    int groups = 1;
    while (groups < B && (B / groups) * bytes_per_batch > (size_t)80 * 1024 * 1024) {
        int next = groups * 2;
        if (B % next != 0) break;
        groups = next;
    }
    const int Bg = B / groups;

    const int TPB = 256;
    const int total1 = Bg * S * C4;
    const int warps2 = Bg * C4;
    dim3 grid1((total1 + TPB - 1) / TPB);
    dim3 grid2((warps2 * 32 + TPB - 1) / TPB);

    for (int grp = 0; grp < groups; grp++) {
        const float4* xg = (const float4*)x + (size_t)grp * Bg * T * C4;
        const float4* ig = (const float4*)init + (size_t)grp * Bg * C4;
        float4* og = (float4*)d_out + (size_t)grp * Bg * T * C4;

        ema_pass1<<<grid1, TPB>>>(xg, smooth, Bg, T, C4, S, L);
        ema_pass2<<<grid2, TPB>>>(ig, smooth, Bg, C4, S, L);
        ema_pass3<<<grid1, TPB>>>(xg, smooth, og, Bg, T, C4, S, L);
    }
}

// round 16
// speedup vs baseline: 1.0122x; 1.0122x over previous
#include <cuda_runtime.h>
#include <cuda_bf16.h>
#include <cstdint>

// EMA: y_t = w*x_t + (1-w)*y_{t-1}, per-channel w, y_{-1} = initial_state.
// inputs [B,T,C] f32, initial_state [B,C] f32, smooth [C] f32 -> out [B,T,C] f32.
//
// Chunked scan exploiting the data-INDEPENDENT decay a = 1-w (segment
// composition factor is analytically a^L).  3 passes per batch-GROUP
// (8 batches = 67 MB < 126 MB L2) so x stays L2-resident between pass1
// and pass3.  R14 ncu: pass1 occ 38.9%, 512 blocks (3.46/SM) -> DRAM 52%.
// R15: S=512 (L=16) doubles items -> 1024 blocks, ~55 warps/SM, finer wave.

#define MAX_SCRATCH (16 * 512 * 64)     // B * S_max * C4  (8 MiB per array)
#define MAXSPL 16

__device__ float4 g_Bseg[MAX_SCRATCH];
__device__ float4 g_carry[MAX_SCRATCH];

static __device__ __forceinline__ float clip01(float v) {
    return fminf(fmaxf(v, 0.0f), 1.0f);
}

static __device__ __forceinline__ float4 f4_pow(float4 base, int e) {
    float4 r = make_float4(1.f, 1.f, 1.f, 1.f);
    while (e) {
        if (e & 1) { r.x *= base.x; r.y *= base.y; r.z *= base.z; r.w *= base.w; }
        base.x *= base.x; base.y *= base.y; base.z *= base.z; base.w *= base.w;
        e >>= 1;
    }
    return r;
}

static __device__ __forceinline__ float4 load_wa(const float* __restrict__ smooth,
                                                 int c4, float4* a_out) {
    float4 w = reinterpret_cast<const float4*>(smooth)[c4];
    w.x = clip01(w.x); w.y = clip01(w.y); w.z = clip01(w.z); w.w = clip01(w.w);
    *a_out = make_float4(1.0f - w.x, 1.0f - w.y, 1.0f - w.z, 1.0f - w.w);
    return w;
}

__global__ void __launch_bounds__(256)
ema_pass1(const float4* __restrict__ x,
          const float* __restrict__ smooth,
          int Bg, int T, int C4, int S, int L) {
    int g = blockIdx.x * blockDim.x + threadIdx.x;
    int total = Bg * S * C4;
    if (g >= total) return;
    int c4  = g % C4;
    int rem = g / C4;
    int s   = rem % S;
    int b   = rem / S;

    float4 a;
    float4 w = load_wa(smooth, c4, &a);

    const float4* p = x + (size_t)(b * T + s * L) * C4 + c4;
    const size_t step = (size_t)C4;
    float4 y = make_float4(0.f, 0.f, 0.f, 0.f);

    for (int t0 = 0; t0 < L; t0 += 8) {
        float4 v[8];
        #pragma unroll
        for (int i = 0; i < 8; i++) v[i] = p[i * step];
        p += 8 * step;
        #pragma unroll
        for (int i = 0; i < 8; i++) {
            y.x = fmaf(a.x, y.x, w.x * v[i].x);
            y.y = fmaf(a.y, y.y, w.y * v[i].y);
            y.z = fmaf(a.z, y.z, w.z * v[i].z);
            y.w = fmaf(a.w, y.w, w.w * v[i].w);
        }
    }
    g_Bseg[(b * S + s) * C4 + c4] = y;
}

// One WARP per (b, c4). Lane owns spl = S/32 consecutive segments (<=16).
__global__ void __launch_bounds__(256)
ema_pass2(const float4* __restrict__ init,
          const float* __restrict__ smooth,
          int Bg, int C4, int S, int L) {
    int warp = (blockIdx.x * blockDim.x + threadIdx.x) >> 5;
    int lane = threadIdx.x & 31;
    int total_warps = Bg * C4;
    if (warp >= total_warps) return;
    int c4 = warp % C4;
    int b  = warp / C4;

    int spl = S >> 5;                 // segments per lane (<= MAXSPL)

    float4 a;
    load_wa(smooth, c4, &a);
    float4 aL = f4_pow(a, L);         // per-segment coefficient
    float4 c  = f4_pow(aL, spl);      // per-lane composite coefficient

    // Load this lane's segment partials (independent loads, MLP = spl)
    float4 Bs[MAXSPL];
    int base = (b * S + lane * spl) * C4 + c4;
    #pragma unroll
    for (int i = 0; i < MAXSPL; i++) {
        if (i < spl) Bs[i] = g_Bseg[base + i * C4];
    }

    // Lane-local composite B over its spl segments
    float4 b8 = make_float4(0.f, 0.f, 0.f, 0.f);
    #pragma unroll
    for (int i = 0; i < MAXSPL; i++) {
        if (i < spl) {
            b8.x = fmaf(aL.x, b8.x, Bs[i].x);
            b8.y = fmaf(aL.y, b8.y, Bs[i].y);
            b8.z = fmaf(aL.z, b8.z, Bs[i].z);
            b8.w = fmaf(aL.w, b8.w, Bs[i].w);
        }
    }

    // Kogge-Stone inclusive scan of B-terms with constant coefficient c
    float4 Bi = b8;
    float4 cd = c;
    #pragma unroll
    for (int d = 1; d < 32; d <<= 1) {
        float4 up;
        up.x = __shfl_up_sync(0xFFFFFFFFu, Bi.x, d);
        up.y = __shfl_up_sync(0xFFFFFFFFu, Bi.y, d);
        up.z = __shfl_up_sync(0xFFFFFFFFu, Bi.z, d);
        up.w = __shfl_up_sync(0xFFFFFFFFu, Bi.w, d);
        if (lane >= d) {
            Bi.x = fmaf(cd.x, up.x, Bi.x);
            Bi.y = fmaf(cd.y, up.y, Bi.y);
            Bi.z = fmaf(cd.z, up.z, Bi.z);
            Bi.w = fmaf(cd.w, up.w, Bi.w);
        }
        cd.x *= cd.x; cd.y *= cd.y; cd.z *= cd.z; cd.w *= cd.w;
    }

    // Exclusive B and analytic exclusive A = c^lane
    float4 Bex;
    Bex.x = __shfl_up_sync(0xFFFFFFFFu, Bi.x, 1);
    Bex.y = __shfl_up_sync(0xFFFFFFFFu, Bi.y, 1);
    Bex.z = __shfl_up_sync(0xFFFFFFFFu, Bi.z, 1);
    Bex.w = __shfl_up_sync(0xFFFFFFFFu, Bi.w, 1);
    if (lane == 0) Bex = make_float4(0.f, 0.f, 0.f, 0.f);
    float4 Aex = f4_pow(c, lane);

    float4 y0 = init[b * C4 + c4];
    float4 carry;
    carry.x = fmaf(Aex.x, y0.x, Bex.x);
    carry.y = fmaf(Aex.y, y0.y, Bex.y);
    carry.z = fmaf(Aex.z, y0.z, Bex.z);
    carry.w = fmaf(Aex.w, y0.w, Bex.w);

    // Write per-segment entry carries for this lane's segments
    #pragma unroll
    for (int i = 0; i < MAXSPL; i++) {
        if (i < spl) {
            g_carry[base + i * C4] = carry;
            carry.x = fmaf(aL.x, carry.x, Bs[i].x);
            carry.y = fmaf(aL.y, carry.y, Bs[i].y);
            carry.z = fmaf(aL.z, carry.z, Bs[i].z);
            carry.w = fmaf(aL.w, carry.w, Bs[i].w);
        }
    }
}

__global__ void __launch_bounds__(256)
ema_pass3(const float4* __restrict__ x,
          const float* __restrict__ smooth,
          float4* __restrict__ out,
          int Bg, int T, int C4, int S, int L) {
    int g = blockIdx.x * blockDim.x + threadIdx.x;
    int total = Bg * S * C4;
    if (g >= total) return;
    int c4  = g % C4;
    int rem = g / C4;
    int s   = rem % S;
    int b   = rem / S;

    float4 a;
    float4 w = load_wa(smooth, c4, &a);

    float4 y = g_carry[(b * S + s) * C4 + c4];

    size_t off = (size_t)(b * T + s * L) * C4 + c4;
    const float4* p = x + off;
    float4* q = out + off;
    const size_t step = (size_t)C4;

    for (int t0 = 0; t0 < L; t0 += 8) {
        float4 v[8];
        #pragma unroll
        for (int i = 0; i < 8; i++) v[i] = __ldcs(p + i * step);  // last use
        p += 8 * step;
        #pragma unroll
        for (int i = 0; i < 8; i++) {
            y.x = fmaf(a.x, y.x, w.x * v[i].x);
            y.y = fmaf(a.y, y.y, w.y * v[i].y);
            y.z = fmaf(a.z, y.z, w.z * v[i].z);
            y.w = fmaf(a.w, y.w, w.w * v[i].w);
            __stcs(q + i * step, y);   // streaming store: don't evict x from L2
        }
        q += 8 * step;
    }
}

extern "C" void kernel_launch(void* const* d_in, const int* in_sizes, int n_in,
                              void* d_out, int out_size) {
    const float* x      = (const float*)d_in[0];  // [B,T,C]
    const float* init   = (const float*)d_in[1];  // [B,C]
    const float* smooth = (const float*)d_in[2];  // [C]

    const int C  = in_sizes[2];
    const int B  = in_sizes[1] / C;
    const int T  = in_sizes[0] / (B * C);
    const int C4 = C / 4;

    // Pick S: multiple of 32 (warp scan), divides T, L multiple of 8,
    // spl <= MAXSPL, fits scratch.  For T=8192 -> S=512, L=16.
    int S = 0;
    for (int cand = 512; cand >= 32; cand >>= 1) {
        if (T % cand == 0 && ((T / cand) % 8 == 0) &&
            (cand >> 5) <= MAXSPL &&
            (long long)B * cand * C4 <= MAX_SCRATCH) { S = cand; break; }
    }
    if (S == 0) S = 32;
    const int L = T / S;

    // Batch groups: smallest split whose group input fits L2 with headroom
    // (<= ~80 MB). For B=16,T=8192,C=256 -> groups=2, Bg=8 (67 MB/group).
    const size_t bytes_per_batch = (size_t)T * C * 4;
    int groups = 1;
    while (groups < B && (B / groups) * bytes_per_batch > (size_t)80 * 1024 * 1024) {
        int next = groups * 2;
        if (B % next != 0) break;
        groups = next;
    }
    const int Bg = B / groups;

    const int TPB = 256;
    const int total1 = Bg * S * C4;
    const int warps2 = Bg * C4;
    dim3 grid1((total1 + TPB - 1) / TPB);
    dim3 grid2((warps2 * 32 + TPB - 1) / TPB);

    for (int grp = 0; grp < groups; grp++) {
        const float4* xg = (const float4*)x + (size_t)grp * Bg * T * C4;
        const float4* ig = (const float4*)init + (size_t)grp * Bg * C4;
        float4* og = (float4*)d_out + (size_t)grp * Bg * T * C4;

        ema_pass1<<<grid1, TPB>>>(xg, smooth, Bg, T, C4, S, L);
        ema_pass2<<<grid2, TPB>>>(ig, smooth, Bg, C4, S, L);
        ema_pass3<<<grid1, TPB>>>(xg, smooth, og, Bg, T, C4, S, L);
    }
}